// round 3
// baseline (speedup 1.0000x reference)
#include <cuda_runtime.h>
#include <cstdint>
#include <cstdio>

// GQA causal attention w/ additive mask, tf32 mma.sync flash-attention.
// Shapes fixed by the problem: B=2, Sq=Skv=2048, Hq=16, Hkv=4, D=128, fp32.

#define LOG2E_F 1.44269504088896340736f

constexpr int Bz  = 2;
constexpr int Sq  = 2048;
constexpr int Skv = 2048;
constexpr int Hq  = 16;
constexpr int Hkv = 4;
constexpr int Dh  = 128;

constexpr int BR = 128;   // q rows per CTA
constexpr int BC = 64;    // kv cols per tile
constexpr int NTHREADS = 256;  // 8 warps, each owns 16 q rows

// smem row strides (floats), chosen for conflict-free fragment access
constexpr int QSTR = 136;
constexpr int KSTR = 136;
constexpr int VSTR = 132;
constexpr int PSTR = 72;

constexpr int Q_FLOATS = BR * QSTR;   // 17408
constexpr int K_FLOATS = BC * KSTR;   // 8704
constexpr int V_FLOATS = BC * VSTR;   // 8448
constexpr int P_FLOATS = BR * PSTR;   // 9216
constexpr int SMEM_FLOATS = Q_FLOATS + K_FLOATS + V_FLOATS + P_FLOATS;
constexpr size_t SMEM_BYTES = (size_t)SMEM_FLOATS * sizeof(float); // 175104

__device__ __forceinline__ float tf32r(float x) {
    unsigned u;
    asm("cvt.rna.tf32.f32 %0, %1;" : "=r"(u) : "f"(x));
    return __uint_as_float(u);
}

__device__ __forceinline__ float ex2f(float x) {
    float y;
    asm("ex2.approx.f32 %0, %1;" : "=f"(y) : "f"(x));
    return y;
}

// m16n8k8 row.col tf32 mma.  aL=(a0,a2) from row r, aH=(a1,a3) from row r+8,
// b=(b0,b1) = (k, k+4) of column n.
__device__ __forceinline__ void mma8(float* c, float2 aL, float2 aH, float2 b) {
    unsigned a0 = __float_as_uint(aL.x);
    unsigned a1 = __float_as_uint(aH.x);
    unsigned a2 = __float_as_uint(aL.y);
    unsigned a3 = __float_as_uint(aH.y);
    unsigned b0 = __float_as_uint(b.x);
    unsigned b1 = __float_as_uint(b.y);
    asm volatile(
        "mma.sync.aligned.m16n8k8.row.col.f32.tf32.tf32.f32 "
        "{%0,%1,%2,%3}, {%4,%5,%6,%7}, {%8,%9}, {%0,%1,%2,%3};\n"
        : "+f"(c[0]), "+f"(c[1]), "+f"(c[2]), "+f"(c[3])
        : "r"(a0), "r"(a1), "r"(a2), "r"(a3), "r"(b0), "r"(b1));
}

__global__ void __launch_bounds__(NTHREADS, 1)
flash_attn_tf32_kernel(const float* __restrict__ q,
                       const float* __restrict__ k,
                       const float* __restrict__ v,
                       const float* __restrict__ mask,
                       float* __restrict__ out)
{
    extern __shared__ float sm[];
    float* Qs = sm;
    float* Ks = Qs + Q_FLOATS;
    float* Vs = Ks + K_FLOATS;
    float* Ps = Vs + V_FLOATS;

    const int tid  = threadIdx.x;
    const int w    = tid >> 5;
    const int lane = tid & 31;
    const int qgrp = lane >> 2;  // 0..7 (fragment row group)
    const int qid  = lane & 3;   // 0..3 (fragment col group)

    const int q0 = blockIdx.x * BR;
    const int h  = blockIdx.y;
    const int b  = blockIdx.z;
    const int hk = h & (Hkv - 1);

    const float qscale = LOG2E_F * 0.08838834764831845f; // log2(e)/sqrt(128)

    // ---- Load Q tile (BR x Dh) into smem, tf32-rounded, k-pair-interleaved ----
    {
        const float* qbase = q + (((size_t)b * Sq + q0) * Hq + h) * Dh;
        #pragma unroll
        for (int i = 0; i < (BR * Dh / 4) / NTHREADS; ++i) { // 16
            int f4  = tid + NTHREADS * i;
            int row = f4 >> 5;
            int c   = (f4 & 31) * 4;
            float4 val = *(const float4*)(qbase + (size_t)row * (Hq * Dh) + c);
            int g = (c >> 3) << 3;
            int p = g + ((c & 4) ? 1 : 0);
            float* dst = Qs + row * QSTR;
            dst[p + 0] = tf32r(val.x * qscale);
            dst[p + 2] = tf32r(val.y * qscale);
            dst[p + 4] = tf32r(val.z * qscale);
            dst[p + 6] = tf32r(val.w * qscale);
        }
    }

    const int lr0 = 16 * w + qgrp;    // CTA-local q row (and +8)
    const int rg0 = q0 + lr0;         // global q row

    float mrow0 = -1e30f, mrow1 = -1e30f;
    float lrow0 = 0.f,    lrow1 = 0.f;
    float O[16][4];
    #pragma unroll
    for (int nt = 0; nt < 16; ++nt) {
        O[nt][0] = 0.f; O[nt][1] = 0.f; O[nt][2] = 0.f; O[nt][3] = 0.f;
    }

    const int rwmax  = q0 + 16 * w + 15;
    const int ntiles = (q0 + BR) / BC;

    const float* kbase = k + (size_t)b * Skv * Hkv * Dh + (size_t)hk * Dh;
    const float* vbase = v + (size_t)b * Skv * Hkv * Dh + (size_t)hk * Dh;
    const float* mbase = mask + ((size_t)(b * Hq + h) * Sq) * Skv;

    const float* qrow0 = Qs + lr0 * QSTR;
    const float* qrow1 = qrow0 + 8 * QSTR;
    float* p0 = Ps + lr0 * PSTR;
    float* p1 = p0 + 8 * PSTR;
    const int pp = ((qid & 1) << 2) + (qid >> 1); // perm position for P stores

    for (int j = 0; j < ntiles; ++j) {
        const int kv0 = j * BC;
        __syncthreads();
        // ---- Load K (interleaved, tf32) and V (plain, tf32) tiles ----
        {
            const float* kb = kbase + (size_t)kv0 * (Hkv * Dh);
            const float* vb = vbase + (size_t)kv0 * (Hkv * Dh);
            #pragma unroll
            for (int i = 0; i < (BC * Dh / 4) / NTHREADS; ++i) { // 8
                int f4  = tid + NTHREADS * i;
                int row = f4 >> 5;
                int c   = (f4 & 31) * 4;
                float4 kv4 = *(const float4*)(kb + (size_t)row * (Hkv * Dh) + c);
                int g = (c >> 3) << 3;
                int p = g + ((c & 4) ? 1 : 0);
                float* kd = Ks + row * KSTR;
                kd[p + 0] = tf32r(kv4.x);
                kd[p + 2] = tf32r(kv4.y);
                kd[p + 4] = tf32r(kv4.z);
                kd[p + 6] = tf32r(kv4.w);
                float4 vv4 = *(const float4*)(vb + (size_t)row * (Hkv * Dh) + c);
                float* vd = Vs + row * VSTR + c;
                vd[0] = tf32r(vv4.x);
                vd[1] = tf32r(vv4.y);
                vd[2] = tf32r(vv4.z);
                vd[3] = tf32r(vv4.w);
            }
        }
        __syncthreads();

        if (kv0 > rwmax) continue;   // whole tile masked for this warp's rows

        // ---- S = Q @ K^T (pre-scaled by log2e/sqrt(D)) ----
        float S[8][4];
        #pragma unroll
        for (int nt = 0; nt < 8; ++nt) {
            S[nt][0] = 0.f; S[nt][1] = 0.f; S[nt][2] = 0.f; S[nt][3] = 0.f;
        }
        #pragma unroll
        for (int kt = 0; kt < 16; ++kt) {
            const int ko = kt * 8 + 2 * qid;
            float2 aL = *(const float2*)(qrow0 + ko);
            float2 aH = *(const float2*)(qrow1 + ko);
            #pragma unroll
            for (int nt = 0; nt < 8; ++nt) {
                float2 bb = *(const float2*)(Ks + (nt * 8 + qgrp) * KSTR + ko);
                mma8(S[nt], aL, aH, bb);
            }
        }

        // ---- softmax update (mask add + causal + online rescale) ----
        const float* m0p = mbase + (size_t)rg0 * Skv + kv0;
        const float* m1p = m0p + (size_t)8 * Skv;
        float mx0 = -1e30f, mx1 = -1e30f;
        #pragma unroll
        for (int nt = 0; nt < 8; ++nt) {
            const int c0 = nt * 8 + 2 * qid;
            float2 mk0 = *(const float2*)(m0p + c0);
            float2 mk1 = *(const float2*)(m1p + c0);
            const int cg = kv0 + c0;
            float s00 = S[nt][0] + LOG2E_F * mk0.x;
            float s01 = S[nt][1] + LOG2E_F * mk0.y;
            float s10 = S[nt][2] + LOG2E_F * mk1.x;
            float s11 = S[nt][3] + LOG2E_F * mk1.y;
            if (cg     > rg0)     s00 = -1e6f;
            if (cg + 1 > rg0)     s01 = -1e6f;
            if (cg     > rg0 + 8) s10 = -1e6f;
            if (cg + 1 > rg0 + 8) s11 = -1e6f;
            S[nt][0] = s00; S[nt][1] = s01; S[nt][2] = s10; S[nt][3] = s11;
            mx0 = fmaxf(mx0, fmaxf(s00, s01));
            mx1 = fmaxf(mx1, fmaxf(s10, s11));
        }
        mx0 = fmaxf(mx0, __shfl_xor_sync(0xffffffffu, mx0, 1));
        mx0 = fmaxf(mx0, __shfl_xor_sync(0xffffffffu, mx0, 2));
        mx1 = fmaxf(mx1, __shfl_xor_sync(0xffffffffu, mx1, 1));
        mx1 = fmaxf(mx1, __shfl_xor_sync(0xffffffffu, mx1, 2));
        const float mn0 = fmaxf(mrow0, mx0);
        const float mn1 = fmaxf(mrow1, mx1);
        const float al0 = ex2f(mrow0 - mn0);
        const float al1 = ex2f(mrow1 - mn1);
        mrow0 = mn0; mrow1 = mn1;

        float sum0 = 0.f, sum1 = 0.f;
        #pragma unroll
        for (int nt = 0; nt < 8; ++nt) {
            float e00 = ex2f(S[nt][0] - mn0);
            float e01 = ex2f(S[nt][1] - mn0);
            float e10 = ex2f(S[nt][2] - mn1);
            float e11 = ex2f(S[nt][3] - mn1);
            sum0 += e00 + e01;
            sum1 += e10 + e11;
            p0[nt * 8 + pp]     = tf32r(e00);
            p0[nt * 8 + pp + 2] = tf32r(e01);
            p1[nt * 8 + pp]     = tf32r(e10);
            p1[nt * 8 + pp + 2] = tf32r(e11);
        }
        sum0 += __shfl_xor_sync(0xffffffffu, sum0, 1);
        sum0 += __shfl_xor_sync(0xffffffffu, sum0, 2);
        sum1 += __shfl_xor_sync(0xffffffffu, sum1, 1);
        sum1 += __shfl_xor_sync(0xffffffffu, sum1, 2);
        lrow0 = lrow0 * al0 + sum0;
        lrow1 = lrow1 * al1 + sum1;
        #pragma unroll
        for (int nt = 0; nt < 16; ++nt) {
            O[nt][0] *= al0; O[nt][1] *= al0;
            O[nt][2] *= al1; O[nt][3] *= al1;
        }
        __syncwarp();

        // ---- O += P @ V ----
        #pragma unroll
        for (int kt = 0; kt < 8; ++kt) {
            const int ko = kt * 8 + 2 * qid;
            float2 aL = *(const float2*)(p0 + ko);
            float2 aH = *(const float2*)(p1 + ko);
            const float* vr0 = Vs + (kt * 8 + qid) * VSTR + qgrp;
            const float* vr1 = vr0 + 4 * VSTR;
            #pragma unroll
            for (int nt = 0; nt < 16; ++nt) {
                float2 bb = make_float2(vr0[nt * 8], vr1[nt * 8]);
                mma8(O[nt], aL, aH, bb);
            }
        }
        __syncwarp();  // protect Ps from next tile's overwrite by quad-mates
    }

    // ---- epilogue: normalize and store ----
    const float inv0 = 1.0f / lrow0;
    const float inv1 = 1.0f / lrow1;
    float* ob0 = out + (((size_t)b * Sq + rg0) * Hq + h) * Dh;
    float* ob1 = ob0 + (size_t)8 * Hq * Dh;
    #pragma unroll
    for (int nt = 0; nt < 16; ++nt) {
        const int c = nt * 8 + 2 * qid;
        *(float2*)(ob0 + c) = make_float2(O[nt][0] * inv0, O[nt][1] * inv0);
        *(float2*)(ob1 + c) = make_float2(O[nt][2] * inv1, O[nt][3] * inv1);
    }
}

extern "C" void kernel_launch(void* const* d_in, const int* in_sizes, int n_in,
                              void* d_out, int out_size) {
    const float* q    = (const float*)d_in[0];
    const float* k    = (const float*)d_in[1];
    const float* v    = (const float*)d_in[2];
    const float* mask = (const float*)d_in[3];
    float* out = (float*)d_out;

    // Idempotent attribute set (not a stream op; safe under graph capture).
    cudaFuncSetAttribute(flash_attn_tf32_kernel,
                         cudaFuncAttributeMaxDynamicSharedMemorySize,
                         (int)SMEM_BYTES);

    dim3 grid(Sq / BR, Hq, Bz);
    flash_attn_tf32_kernel<<<grid, NTHREADS, SMEM_BYTES>>>(q, k, v, mask, out);
}